// round 12
// baseline (speedup 1.0000x reference)
#include <cuda_runtime.h>
#include <cuda_fp16.h>

#define MAXN 100000
#define MAXE 800000

// ---- scratch (device globals; no runtime allocation allowed) ----
// g_svh: per node 128 halves, channel-interleaved: [a0,v0,a1,v1,...,a63,v63]
__device__ __align__(16) __half g_svh [MAXN * 128];
__device__ __align__(16) float  g_denom[MAXN * 64];   // self-loop seed (exp)
__device__ __align__(16) float  g_outh [MAXN * 64];   // seed -> final t
__device__ __align__(16) float4 g_pos4[MAXN];
__device__ int g_cnt [MAXN];      // in-degree (left ZERO by aggregate for next call)
__device__ int g_off [MAXN];      // segment starts (advanced to end by scatter)
__device__ int g_srcs[MAXE];      // src ids grouped by dst
__device__ int g_total;           // bump allocator (reset by proj block 0)

// ---- packed f32x2 helpers (sm_103a packed float pipe) ----
union F2U { float2 f; unsigned long long u; };
__device__ __forceinline__ float2 ffma2(float2 a, float2 b, float2 c) {
    F2U A, B, C, D; A.f = a; B.f = b; C.f = c;
    asm("fma.rn.f32x2 %0, %1, %2, %3;" : "=l"(D.u) : "l"(A.u), "l"(B.u), "l"(C.u));
    return D.f;
}
__device__ __forceinline__ float2 fadd2(float2 a, float2 b) {
    F2U A, B, D; A.f = a; B.f = b;
    asm("add.rn.f32x2 %0, %1, %2;" : "=l"(D.u) : "l"(A.u), "l"(B.u));
    return D.f;
}

// ---------------- proj (+ fused hist in extra blocks) ----------------
__global__ void __launch_bounds__(256) proj_kernel(
        const float* __restrict__ x,
        const float* __restrict__ pos,
        const int*   __restrict__ ei,
        const float* __restrict__ Wl,
        const float* __restrict__ Wsrc,
        const float* __restrict__ bpos,
        int N, int E, int nodeBlocks) {
    if ((int)blockIdx.x >= nodeBlocks) {
        int eb = blockIdx.x - nodeBlocks;
        int e0 = eb * 1024 + threadIdx.x;
#pragma unroll
        for (int k = 0; k < 4; k++) {
            int e = e0 + k * 256;
            if (e < E) atomicAdd(&g_cnt[ei[E + e]], 1);
        }
        return;
    }

    __shared__ float sWs[64 * 64];
    __shared__ float sWl[64 * 64];
    __shared__ float sx [64 * 68];

    int tid  = threadIdx.x;
    int base = blockIdx.x * 64;

    if (blockIdx.x == 0 && tid == 0) g_total = 0;
    if (tid < 64) {
        int node = base + tid;
        if (node < N)
            g_pos4[node] = make_float4(pos[node * 3 + 0], pos[node * 3 + 1],
                                       pos[node * 3 + 2], 0.f);
    }

    for (int g = tid; g < 4096; g += 256) {
        int h = g >> 10, k = (g >> 4) & 63, hd = g & 15;
        int o = h * 16 + hd;
        sWs[k * 64 + o] = Wsrc[g];
        sWl[k * 64 + o] = Wl[g];
    }
    for (int i = tid; i < 1024; i += 256) {
        int n = i >> 4, c4 = i & 15;
        int node = base + n;
        float4 xv = (node < N) ? *(const float4*)(x + (size_t)node * 64 + c4 * 4)
                               : make_float4(0.f, 0.f, 0.f, 0.f);
        int c = c4 * 4;
        sx[(c + 0) * 68 + n] = xv.x;
        sx[(c + 1) * 68 + n] = xv.y;
        sx[(c + 2) * 68 + n] = xv.z;
        sx[(c + 3) * 68 + n] = xv.w;
    }
    __syncthreads();

    int cg = tid & 15, ng = tid >> 4;
    float4 accS[4], accV[4];
#pragma unroll
    for (int i = 0; i < 4; i++) {
        accS[i] = make_float4(0.f, 0.f, 0.f, 0.f);
        accV[i] = make_float4(0.f, 0.f, 0.f, 0.f);
    }

#pragma unroll 8
    for (int k = 0; k < 64; k++) {
        float4 ws = *(float4*)(sWs + k * 64 + cg * 4);
        float4 wl = *(float4*)(sWl + k * 64 + cg * 4);
        float4 xa = *(float4*)(sx + k * 68 + ng * 4);
        float xv[4] = {xa.x, xa.y, xa.z, xa.w};
#pragma unroll
        for (int i = 0; i < 4; i++) {
            accS[i].x += xv[i] * ws.x;
            accS[i].y += xv[i] * ws.y;
            accS[i].z += xv[i] * ws.z;
            accS[i].w += xv[i] * ws.w;
            accV[i].x += xv[i] * wl.x;
            accV[i].y += xv[i] * wl.y;
            accV[i].z += xv[i] * wl.z;
            accV[i].w += xv[i] * wl.w;
        }
    }

    float4 b4 = *(const float4*)(bpos + cg * 4);

#pragma unroll
    for (int i = 0; i < 4; i++) {
        int node = base + ng * 4 + i;
        if (node < N) {
            uint4 o;
            *(__half2*)&o.x = __float22half2_rn(make_float2(accS[i].x, accV[i].x));
            *(__half2*)&o.y = __float22half2_rn(make_float2(accS[i].y, accV[i].y));
            *(__half2*)&o.z = __float22half2_rn(make_float2(accS[i].z, accV[i].z));
            *(__half2*)&o.w = __float22half2_rn(make_float2(accS[i].w, accV[i].w));
            *(uint4*)(g_svh + (size_t)node * 128 + cg * 8) = o;

            // self-loop seed: ex = exp(bpos - a_src); outh = ex*(v + bpos)
            float4 ex, m;
            ex.x = __expf(b4.x - accS[i].x);
            ex.y = __expf(b4.y - accS[i].y);
            ex.z = __expf(b4.z - accS[i].z);
            ex.w = __expf(b4.w - accS[i].w);
            m.x = ex.x * (accV[i].x + b4.x);
            m.y = ex.y * (accV[i].y + b4.y);
            m.z = ex.z * (accV[i].z + b4.z);
            m.w = ex.w * (accV[i].w + b4.w);
            *(float4*)(g_denom + (size_t)node * 64 + cg * 4) = ex;
            *(float4*)(g_outh  + (size_t)node * 64 + cg * 4) = m;
        }
    }
}

// ---------------- one-kernel segment allocation (atomic-bump scan) ----------
__global__ void alloc_kernel(int n) {
    __shared__ int ws[32];
    __shared__ int sbase;
    int i = blockIdx.x * 1024 + threadIdx.x;
    int v = (i < n) ? g_cnt[i] : 0;
    int lane = threadIdx.x & 31, w = threadIdx.x >> 5;
    int xi = v;
#pragma unroll
    for (int o = 1; o < 32; o <<= 1) {
        int t = __shfl_up_sync(~0u, xi, o);
        if (lane >= o) xi += t;
    }
    if (lane == 31) ws[w] = xi;
    __syncthreads();
    if (w == 0) {
        int y = ws[lane];
#pragma unroll
        for (int o = 1; o < 32; o <<= 1) {
            int t = __shfl_up_sync(~0u, y, o);
            if (lane >= o) y += t;
        }
        ws[lane] = y;
    }
    __syncthreads();
    if (threadIdx.x == 0) sbase = atomicAdd(&g_total, ws[31]);
    __syncthreads();
    if (i < n) g_off[i] = sbase + (w > 0 ? ws[w - 1] : 0) + xi - v;  // exclusive
}

__global__ void scatter_kernel(const int* __restrict__ ei, int E) {
    int e = blockIdx.x * 256 + threadIdx.x;
    if (e < E) {
        int d = ei[E + e];
        int idx = atomicAdd(&g_off[d], 1);   // g_off ends at segment end
        g_srcs[idx] = ei[e];
    }
}

// ---------------- aggregate: TWO nodes per warp ----------------
// half-warp (16 lanes) per node, 4 channels per lane.
__device__ __forceinline__ void edge_acc4(
        const float4& pd, const float4& ps, uint4 u,
        const float4& wx, const float4& wy, const float4& wz, const float4& bb,
        float4& accD, float4& accM) {
    float rx = pd.x - ps.x, ry = pd.y - ps.y, rz = pd.z - ps.z;
    float2 rx2 = make_float2(rx, rx);
    float2 ry2 = make_float2(ry, ry);
    float2 rz2 = make_float2(rz, rz);
    float2 dl01 = ffma2(rx2, make_float2(wx.x, wx.y),
                  ffma2(ry2, make_float2(wy.x, wy.y),
                  ffma2(rz2, make_float2(wz.x, wz.y), make_float2(bb.x, bb.y))));
    float2 dl23 = ffma2(rx2, make_float2(wx.z, wx.w),
                  ffma2(ry2, make_float2(wy.z, wy.w),
                  ffma2(rz2, make_float2(wz.z, wz.w), make_float2(bb.z, bb.w))));
    float2 q0 = __half22float2(*(__half2*)&u.x);   // (a0, v0)
    float2 q1 = __half22float2(*(__half2*)&u.y);   // (a1, v1)
    float2 q2 = __half22float2(*(__half2*)&u.z);   // (a2, v2)
    float2 q3 = __half22float2(*(__half2*)&u.w);   // (a3, v3)
    float2 ex01 = make_float2(__expf(dl01.x - q0.x), __expf(dl01.y - q1.x));
    float2 ex23 = make_float2(__expf(dl23.x - q2.x), __expf(dl23.y - q3.x));
    float2 aD01 = fadd2(make_float2(accD.x, accD.y), ex01);
    float2 aD23 = fadd2(make_float2(accD.z, accD.w), ex23);
    float2 aM01 = ffma2(ex01, fadd2(make_float2(q0.y, q1.y), dl01),
                        make_float2(accM.x, accM.y));
    float2 aM23 = ffma2(ex23, fadd2(make_float2(q2.y, q3.y), dl23),
                        make_float2(accM.z, accM.w));
    accD = make_float4(aD01.x, aD01.y, aD23.x, aD23.y);
    accM = make_float4(aM01.x, aM01.y, aM23.x, aM23.y);
}

__global__ void __launch_bounds__(256) aggregate_kernel(
        const float* __restrict__ Wpos,
        const float* __restrict__ bpos,
        int N) {
    int warpId = (blockIdx.x * 256 + threadIdx.x) >> 5;
    int lane   = threadIdx.x & 31;
    int half16 = lane & 16;          // 0 or 16
    int lane16 = lane & 15;
    int d = warpId * 2 + (half16 >> 4);
    bool active = (d < N);
    if (__ballot_sync(~0u, active) == 0) return;
    int dd = active ? d : 0;

    int c0 = lane16 * 4;
    int h = c0 >> 4, hd = c0 & 15;
    float4 wx = *(const float4*)(Wpos + h * 48 + hd);
    float4 wy = *(const float4*)(Wpos + h * 48 + 16 + hd);
    float4 wz = *(const float4*)(Wpos + h * 48 + 32 + hd);
    float4 bb = *(const float4*)(bpos + h * 16 + hd);

    float4 pd = g_pos4[dd];
    int end   = g_off[dd];           // advanced to end by scatter
    int cnt   = active ? g_cnt[dd] : 0;
    int start = end - cnt;
    if (lane16 == 0 && active) g_cnt[dd] = 0;   // self-clean for next call

    // seed with self-loop contribution written by proj
    float4 accD = *(float4*)(g_denom + (size_t)dd * 64 + c0);
    float4 accM = *(float4*)(g_outh  + (size_t)dd * 64 + c0);

    int cntO   = __shfl_xor_sync(~0u, cnt, 16);
    int cntMax = max(cnt, cntO);

    for (int base = 0; base < cntMax; base += 16) {
        int m    = min(16, cnt - base);        // may be <= 0
        int mMax = min(16, cntMax - base);
        int myS  = (lane16 < m) ? g_srcs[start + base + lane16] : dd;  // coalesced
        int j = 0;
        for (; j + 2 <= mMax; j += 2) {
            int s0 = __shfl_sync(~0u, myS, half16 + j);
            int s1 = __shfl_sync(~0u, myS, half16 + j + 1);
            float4 p0 = g_pos4[s0];
            float4 p1 = g_pos4[s1];
            uint4 u0 = *(const uint4*)(g_svh + (size_t)s0 * 128 + c0 * 2);
            uint4 u1 = *(const uint4*)(g_svh + (size_t)s1 * 128 + c0 * 2);
            if (j < m)     edge_acc4(pd, p0, u0, wx, wy, wz, bb, accD, accM);
            if (j + 1 < m) edge_acc4(pd, p1, u1, wx, wy, wz, bb, accD, accM);
        }
        if (j < mMax) {
            int s0 = __shfl_sync(~0u, myS, half16 + j);
            float4 p0 = g_pos4[s0];
            uint4 u0 = *(const uint4*)(g_svh + (size_t)s0 * 128 + c0 * 2);
            if (j < m) edge_acc4(pd, p0, u0, wx, wy, wz, bb, accD, accM);
        }
    }

    if (active) {
        // fused softmax normalization: store t = accM / accD
        float4 t;
        t.x = accM.x / accD.x;
        t.y = accM.y / accD.y;
        t.z = accM.z / accD.z;
        t.w = accM.w / accD.w;
        *(float4*)(g_outh + (size_t)d * 64 + c0) = t;
    }
}

// ---------------- MLP: y = relu(t@W1+b1)@W2+b2  (t already normalized) ------
__global__ void __launch_bounds__(256) mlp_kernel(
        const float* __restrict__ W1,
        const float* __restrict__ b1,
        const float* __restrict__ W2,
        const float* __restrict__ b2,
        float* __restrict__ out, int N) {
    __shared__ float sW1[64 * 64];
    __shared__ float sW2[64 * 64];
    __shared__ float sx [64 * 68];
    int tid  = threadIdx.x;
    int base = blockIdx.x * 64;

    for (int g = tid; g < 4096; g += 256) { sW1[g] = W1[g]; sW2[g] = W2[g]; }

    for (int i = tid; i < 1024; i += 256) {
        int n = i >> 4, c4 = i & 15;
        int node = base + n;
        float4 o4 = (node < N) ? ((const float4*)g_outh)[(size_t)node * 16 + c4]
                               : make_float4(0.f, 0.f, 0.f, 0.f);
        int c = c4 * 4;
        sx[(c + 0) * 68 + n] = o4.x;
        sx[(c + 1) * 68 + n] = o4.y;
        sx[(c + 2) * 68 + n] = o4.z;
        sx[(c + 3) * 68 + n] = o4.w;
    }
    __syncthreads();

    int cg = tid & 15, ng = tid >> 4;
    float4 bias = *(const float4*)(b1 + cg * 4);
    float4 acc[4];
#pragma unroll
    for (int i = 0; i < 4; i++) acc[i] = bias;

#pragma unroll 8
    for (int k = 0; k < 64; k++) {
        float4 w  = *(float4*)(sW1 + k * 64 + cg * 4);
        float4 xa = *(float4*)(sx + k * 68 + ng * 4);
        float xv[4] = {xa.x, xa.y, xa.z, xa.w};
#pragma unroll
        for (int i = 0; i < 4; i++) {
            acc[i].x += xv[i] * w.x;
            acc[i].y += xv[i] * w.y;
            acc[i].z += xv[i] * w.z;
            acc[i].w += xv[i] * w.w;
        }
    }
    __syncthreads();

#pragma unroll
    for (int i = 0; i < 4; i++) {
        int n = ng * 4 + i;
        sx[(cg * 4 + 0) * 68 + n] = fmaxf(acc[i].x, 0.f);
        sx[(cg * 4 + 1) * 68 + n] = fmaxf(acc[i].y, 0.f);
        sx[(cg * 4 + 2) * 68 + n] = fmaxf(acc[i].z, 0.f);
        sx[(cg * 4 + 3) * 68 + n] = fmaxf(acc[i].w, 0.f);
    }
    __syncthreads();

    float4 bias2 = *(const float4*)(b2 + cg * 4);
#pragma unroll
    for (int i = 0; i < 4; i++) acc[i] = bias2;

#pragma unroll 8
    for (int k = 0; k < 64; k++) {
        float4 w  = *(float4*)(sW2 + k * 64 + cg * 4);
        float4 xa = *(float4*)(sx + k * 68 + ng * 4);
        float xv[4] = {xa.x, xa.y, xa.z, xa.w};
#pragma unroll
        for (int i = 0; i < 4; i++) {
            acc[i].x += xv[i] * w.x;
            acc[i].y += xv[i] * w.y;
            acc[i].z += xv[i] * w.z;
            acc[i].w += xv[i] * w.w;
        }
    }
#pragma unroll
    for (int i = 0; i < 4; i++) {
        int node = base + ng * 4 + i;
        if (node < N)
            *(float4*)(out + (size_t)node * 64 + cg * 4) = acc[i];
    }
}

extern "C" void kernel_launch(void* const* d_in, const int* in_sizes, int n_in,
                              void* d_out, int out_size) {
    const float* x    = (const float*)d_in[0];
    const float* pos  = (const float*)d_in[1];
    const int*   ei   = (const int*)d_in[2];
    const float* Wl   = (const float*)d_in[3];
    const float* Wsrc = (const float*)d_in[4];
    // d_in[5] = W_dst  (unused: cancels exactly in the segment softmax)
    const float* Wpos = (const float*)d_in[6];
    const float* bpos = (const float*)d_in[7];
    const float* W1   = (const float*)d_in[8];
    const float* b1   = (const float*)d_in[9];
    const float* W2   = (const float*)d_in[10];
    const float* b2   = (const float*)d_in[11];
    float* out = (float*)d_out;

    int N  = in_sizes[0] / 64;
    int E  = in_sizes[2] / 2;

    int nodeBlocks = (N + 63) / 64;
    int histBlocks = (E + 1023) / 1024;
    proj_kernel<<<nodeBlocks + histBlocks, 256>>>(x, pos, ei, Wl, Wsrc, bpos,
                                                  N, E, nodeBlocks);

    alloc_kernel<<<(N + 1023) / 1024, 1024>>>(N);

    scatter_kernel<<<(E + 255) / 256, 256>>>(ei, E);

    int nwarps = (N + 1) / 2;
    aggregate_kernel<<<(nwarps * 32 + 255) / 256, 256>>>(Wpos, bpos, N);

    mlp_kernel<<<(N + 63) / 64, 256>>>(W1, b1, W2, b2, out, N);
}

// round 13
// speedup vs baseline: 1.0145x; 1.0145x over previous
#include <cuda_runtime.h>
#include <cuda_fp16.h>

#define MAXN 100000
#define MAXE 800000

// ---- scratch (device globals; no runtime allocation allowed) ----
// g_svh: per node 128 halves, channel-interleaved: [a0,v0,a1,v1,...,a63,v63]
__device__ __align__(16) __half g_svh [MAXN * 128];
__device__ __align__(16) float  g_denom[MAXN * 64];   // self-loop seed (exp)
__device__ __align__(16) float  g_outh [MAXN * 64];   // seed -> final t
__device__ __align__(16) float4 g_pos4[MAXN];
__device__ int g_cnt [MAXN];      // in-degree (left ZERO by aggregate for next call)
__device__ int g_off [MAXN];      // segment starts (advanced to end by scatter)
__device__ int g_srcs[MAXE];      // src ids grouped by dst
__device__ int g_total;           // bump allocator (reset by proj block 0)

// ---- packed f32x2 helpers (sm_103a packed float pipe) ----
union F2U { float2 f; unsigned long long u; };
__device__ __forceinline__ float2 ffma2(float2 a, float2 b, float2 c) {
    F2U A, B, C, D; A.f = a; B.f = b; C.f = c;
    asm("fma.rn.f32x2 %0, %1, %2, %3;" : "=l"(D.u) : "l"(A.u), "l"(B.u), "l"(C.u));
    return D.f;
}
__device__ __forceinline__ float2 fadd2(float2 a, float2 b) {
    F2U A, B, D; A.f = a; B.f = b;
    asm("add.rn.f32x2 %0, %1, %2;" : "=l"(D.u) : "l"(A.u), "l"(B.u));
    return D.f;
}

// ---------------- proj (+ fused hist in extra blocks) ----------------
__global__ void __launch_bounds__(256) proj_kernel(
        const float* __restrict__ x,
        const float* __restrict__ pos,
        const int*   __restrict__ ei,
        const float* __restrict__ Wl,
        const float* __restrict__ Wsrc,
        const float* __restrict__ bpos,
        int N, int E, int nodeBlocks) {
    if ((int)blockIdx.x >= nodeBlocks) {
        int eb = blockIdx.x - nodeBlocks;
        int e0 = eb * 1024 + threadIdx.x;
#pragma unroll
        for (int k = 0; k < 4; k++) {
            int e = e0 + k * 256;
            if (e < E) atomicAdd(&g_cnt[ei[E + e]], 1);
        }
        return;
    }

    __shared__ float sWs[64 * 64];
    __shared__ float sWl[64 * 64];
    __shared__ float sx [64 * 68];

    int tid  = threadIdx.x;
    int base = blockIdx.x * 64;

    if (blockIdx.x == 0 && tid == 0) g_total = 0;
    if (tid < 64) {
        int node = base + tid;
        if (node < N)
            g_pos4[node] = make_float4(pos[node * 3 + 0], pos[node * 3 + 1],
                                       pos[node * 3 + 2], 0.f);
    }

    for (int g = tid; g < 4096; g += 256) {
        int h = g >> 10, k = (g >> 4) & 63, hd = g & 15;
        int o = h * 16 + hd;
        sWs[k * 64 + o] = Wsrc[g];
        sWl[k * 64 + o] = Wl[g];
    }
    for (int i = tid; i < 1024; i += 256) {
        int n = i >> 4, c4 = i & 15;
        int node = base + n;
        float4 xv = (node < N) ? *(const float4*)(x + (size_t)node * 64 + c4 * 4)
                               : make_float4(0.f, 0.f, 0.f, 0.f);
        int c = c4 * 4;
        sx[(c + 0) * 68 + n] = xv.x;
        sx[(c + 1) * 68 + n] = xv.y;
        sx[(c + 2) * 68 + n] = xv.z;
        sx[(c + 3) * 68 + n] = xv.w;
    }
    __syncthreads();

    int cg = tid & 15, ng = tid >> 4;
    float4 accS[4], accV[4];
#pragma unroll
    for (int i = 0; i < 4; i++) {
        accS[i] = make_float4(0.f, 0.f, 0.f, 0.f);
        accV[i] = make_float4(0.f, 0.f, 0.f, 0.f);
    }

#pragma unroll 8
    for (int k = 0; k < 64; k++) {
        float4 ws = *(float4*)(sWs + k * 64 + cg * 4);
        float4 wl = *(float4*)(sWl + k * 64 + cg * 4);
        float4 xa = *(float4*)(sx + k * 68 + ng * 4);
        float xv[4] = {xa.x, xa.y, xa.z, xa.w};
#pragma unroll
        for (int i = 0; i < 4; i++) {
            accS[i].x += xv[i] * ws.x;
            accS[i].y += xv[i] * ws.y;
            accS[i].z += xv[i] * ws.z;
            accS[i].w += xv[i] * ws.w;
            accV[i].x += xv[i] * wl.x;
            accV[i].y += xv[i] * wl.y;
            accV[i].z += xv[i] * wl.z;
            accV[i].w += xv[i] * wl.w;
        }
    }

    float4 b4 = *(const float4*)(bpos + cg * 4);

#pragma unroll
    for (int i = 0; i < 4; i++) {
        int node = base + ng * 4 + i;
        if (node < N) {
            uint4 o;
            *(__half2*)&o.x = __float22half2_rn(make_float2(accS[i].x, accV[i].x));
            *(__half2*)&o.y = __float22half2_rn(make_float2(accS[i].y, accV[i].y));
            *(__half2*)&o.z = __float22half2_rn(make_float2(accS[i].z, accV[i].z));
            *(__half2*)&o.w = __float22half2_rn(make_float2(accS[i].w, accV[i].w));
            *(uint4*)(g_svh + (size_t)node * 128 + cg * 8) = o;

            // self-loop seed: ex = exp(bpos - a_src); outh = ex*(v + bpos)
            float4 ex, m;
            ex.x = __expf(b4.x - accS[i].x);
            ex.y = __expf(b4.y - accS[i].y);
            ex.z = __expf(b4.z - accS[i].z);
            ex.w = __expf(b4.w - accS[i].w);
            m.x = ex.x * (accV[i].x + b4.x);
            m.y = ex.y * (accV[i].y + b4.y);
            m.z = ex.z * (accV[i].z + b4.z);
            m.w = ex.w * (accV[i].w + b4.w);
            *(float4*)(g_denom + (size_t)node * 64 + cg * 4) = ex;
            *(float4*)(g_outh  + (size_t)node * 64 + cg * 4) = m;
        }
    }
}

// ---------------- one-kernel segment allocation (atomic-bump scan) ----------
__global__ void alloc_kernel(int n) {
    __shared__ int ws[32];
    __shared__ int sbase;
    int i = blockIdx.x * 1024 + threadIdx.x;
    int v = (i < n) ? g_cnt[i] : 0;
    int lane = threadIdx.x & 31, w = threadIdx.x >> 5;
    int xi = v;
#pragma unroll
    for (int o = 1; o < 32; o <<= 1) {
        int t = __shfl_up_sync(~0u, xi, o);
        if (lane >= o) xi += t;
    }
    if (lane == 31) ws[w] = xi;
    __syncthreads();
    if (w == 0) {
        int y = ws[lane];
#pragma unroll
        for (int o = 1; o < 32; o <<= 1) {
            int t = __shfl_up_sync(~0u, y, o);
            if (lane >= o) y += t;
        }
        ws[lane] = y;
    }
    __syncthreads();
    if (threadIdx.x == 0) sbase = atomicAdd(&g_total, ws[31]);
    __syncthreads();
    if (i < n) g_off[i] = sbase + (w > 0 ? ws[w - 1] : 0) + xi - v;  // exclusive
}

__global__ void scatter_kernel(const int* __restrict__ ei, int E) {
    int e = blockIdx.x * 256 + threadIdx.x;
    if (e < E) {
        int d = ei[E + e];
        int idx = atomicAdd(&g_off[d], 1);   // g_off ends at segment end
        g_srcs[idx] = ei[e];
    }
}

// ---------------- aggregate: one warp per destination node ----------------
// lane handles channels (2*lane, 2*lane+1).
__device__ __forceinline__ void edge_acc(
        const float4& pd, const float4& ps, uint2 u,
        const float2& wx, const float2& wy, const float2& wz, const float2& bb,
        float2& accD, float2& accM) {
    float rx = pd.x - ps.x, ry = pd.y - ps.y, rz = pd.z - ps.z;
    float2 dl = ffma2(make_float2(rx, rx), wx,
                ffma2(make_float2(ry, ry), wy,
                ffma2(make_float2(rz, rz), wz, bb)));
    float2 q0 = __half22float2(*(__half2*)&u.x);   // (a_c0, v_c0)
    float2 q1 = __half22float2(*(__half2*)&u.y);   // (a_c1, v_c1)
    float2 ex = make_float2(__expf(dl.x - q0.x), __expf(dl.y - q1.x));
    float2 vv = make_float2(q0.y, q1.y);
    accD = fadd2(accD, ex);
    accM = ffma2(ex, fadd2(vv, dl), accM);
}

__global__ void __launch_bounds__(256) aggregate_kernel(
        const float* __restrict__ Wpos,
        const float* __restrict__ bpos,
        int N) {
    int d    = (blockIdx.x * 256 + threadIdx.x) >> 5;
    int lane = threadIdx.x & 31;
    if (d >= N) return;

    int c0 = lane * 2;
    int h = c0 >> 4, hd = c0 & 15;
    float2 wx = *(const float2*)(Wpos + h * 48 + hd);
    float2 wy = *(const float2*)(Wpos + h * 48 + 16 + hd);
    float2 wz = *(const float2*)(Wpos + h * 48 + 32 + hd);
    float2 bb = *(const float2*)(bpos + h * 16 + hd);

    float4 pd = g_pos4[d];
    int end   = g_off[d];        // advanced to end by scatter
    int cnt   = g_cnt[d];
    int start = end - cnt;
    if (lane == 0) g_cnt[d] = 0;     // self-clean for the next call's histogram

    // seed with self-loop contribution written by proj
    float2 accD = *(float2*)(g_denom + (size_t)d * 64 + c0);
    float2 accM = *(float2*)(g_outh  + (size_t)d * 64 + c0);

    for (int base = 0; base < cnt; base += 32) {
        int m = cnt - base; if (m > 32) m = 32;
        int myS = (lane < m) ? g_srcs[start + base + lane] : 0;  // coalesced
        int j = 0;
        for (; j + 4 <= m; j += 4) {
            int s0 = __shfl_sync(~0u, myS, j + 0);
            int s1 = __shfl_sync(~0u, myS, j + 1);
            int s2 = __shfl_sync(~0u, myS, j + 2);
            int s3 = __shfl_sync(~0u, myS, j + 3);
            float4 p0 = g_pos4[s0];
            float4 p1 = g_pos4[s1];
            float4 p2 = g_pos4[s2];
            float4 p3 = g_pos4[s3];
            uint2 u0 = *(const uint2*)(g_svh + (size_t)s0 * 128 + c0 * 2);
            uint2 u1 = *(const uint2*)(g_svh + (size_t)s1 * 128 + c0 * 2);
            uint2 u2 = *(const uint2*)(g_svh + (size_t)s2 * 128 + c0 * 2);
            uint2 u3 = *(const uint2*)(g_svh + (size_t)s3 * 128 + c0 * 2);
            edge_acc(pd, p0, u0, wx, wy, wz, bb, accD, accM);
            edge_acc(pd, p1, u1, wx, wy, wz, bb, accD, accM);
            edge_acc(pd, p2, u2, wx, wy, wz, bb, accD, accM);
            edge_acc(pd, p3, u3, wx, wy, wz, bb, accD, accM);
        }
        for (; j < m; j++) {
            int s0 = __shfl_sync(~0u, myS, j);
            float4 p0 = g_pos4[s0];
            uint2 u0 = *(const uint2*)(g_svh + (size_t)s0 * 128 + c0 * 2);
            edge_acc(pd, p0, u0, wx, wy, wz, bb, accD, accM);
        }
    }

    // fused softmax normalization: store t = accM / accD (mlp reads t only)
    float2 t;
    t.x = accM.x / accD.x;
    t.y = accM.y / accD.y;
    *(float2*)(g_outh + (size_t)d * 64 + c0) = t;
}

// ---------------- MLP: y = relu(t@W1+b1)@W2+b2  (t already normalized) ------
__global__ void __launch_bounds__(256) mlp_kernel(
        const float* __restrict__ W1,
        const float* __restrict__ b1,
        const float* __restrict__ W2,
        const float* __restrict__ b2,
        float* __restrict__ out, int N) {
    __shared__ float sW1[64 * 64];
    __shared__ float sW2[64 * 64];
    __shared__ float sx [64 * 68];
    int tid  = threadIdx.x;
    int base = blockIdx.x * 64;

    for (int g = tid; g < 4096; g += 256) { sW1[g] = W1[g]; sW2[g] = W2[g]; }

    for (int i = tid; i < 1024; i += 256) {
        int n = i >> 4, c4 = i & 15;
        int node = base + n;
        float4 o4 = (node < N) ? ((const float4*)g_outh)[(size_t)node * 16 + c4]
                               : make_float4(0.f, 0.f, 0.f, 0.f);
        int c = c4 * 4;
        sx[(c + 0) * 68 + n] = o4.x;
        sx[(c + 1) * 68 + n] = o4.y;
        sx[(c + 2) * 68 + n] = o4.z;
        sx[(c + 3) * 68 + n] = o4.w;
    }
    __syncthreads();

    int cg = tid & 15, ng = tid >> 4;
    float4 bias = *(const float4*)(b1 + cg * 4);
    float4 acc[4];
#pragma unroll
    for (int i = 0; i < 4; i++) acc[i] = bias;

#pragma unroll 8
    for (int k = 0; k < 64; k++) {
        float4 w  = *(float4*)(sW1 + k * 64 + cg * 4);
        float4 xa = *(float4*)(sx + k * 68 + ng * 4);
        float xv[4] = {xa.x, xa.y, xa.z, xa.w};
#pragma unroll
        for (int i = 0; i < 4; i++) {
            acc[i].x += xv[i] * w.x;
            acc[i].y += xv[i] * w.y;
            acc[i].z += xv[i] * w.z;
            acc[i].w += xv[i] * w.w;
        }
    }
    __syncthreads();

#pragma unroll
    for (int i = 0; i < 4; i++) {
        int n = ng * 4 + i;
        sx[(cg * 4 + 0) * 68 + n] = fmaxf(acc[i].x, 0.f);
        sx[(cg * 4 + 1) * 68 + n] = fmaxf(acc[i].y, 0.f);
        sx[(cg * 4 + 2) * 68 + n] = fmaxf(acc[i].z, 0.f);
        sx[(cg * 4 + 3) * 68 + n] = fmaxf(acc[i].w, 0.f);
    }
    __syncthreads();

    float4 bias2 = *(const float4*)(b2 + cg * 4);
#pragma unroll
    for (int i = 0; i < 4; i++) acc[i] = bias2;

#pragma unroll 8
    for (int k = 0; k < 64; k++) {
        float4 w  = *(float4*)(sW2 + k * 64 + cg * 4);
        float4 xa = *(float4*)(sx + k * 68 + ng * 4);
        float xv[4] = {xa.x, xa.y, xa.z, xa.w};
#pragma unroll
        for (int i = 0; i < 4; i++) {
            acc[i].x += xv[i] * w.x;
            acc[i].y += xv[i] * w.y;
            acc[i].z += xv[i] * w.z;
            acc[i].w += xv[i] * w.w;
        }
    }
#pragma unroll
    for (int i = 0; i < 4; i++) {
        int node = base + ng * 4 + i;
        if (node < N)
            *(float4*)(out + (size_t)node * 64 + cg * 4) = acc[i];
    }
}

extern "C" void kernel_launch(void* const* d_in, const int* in_sizes, int n_in,
                              void* d_out, int out_size) {
    const float* x    = (const float*)d_in[0];
    const float* pos  = (const float*)d_in[1];
    const int*   ei   = (const int*)d_in[2];
    const float* Wl   = (const float*)d_in[3];
    const float* Wsrc = (const float*)d_in[4];
    // d_in[5] = W_dst  (unused: cancels exactly in the segment softmax)
    const float* Wpos = (const float*)d_in[6];
    const float* bpos = (const float*)d_in[7];
    const float* W1   = (const float*)d_in[8];
    const float* b1   = (const float*)d_in[9];
    const float* W2   = (const float*)d_in[10];
    const float* b2   = (const float*)d_in[11];
    float* out = (float*)d_out;

    int N  = in_sizes[0] / 64;
    int E  = in_sizes[2] / 2;

    int nodeBlocks = (N + 63) / 64;
    int histBlocks = (E + 1023) / 1024;
    proj_kernel<<<nodeBlocks + histBlocks, 256>>>(x, pos, ei, Wl, Wsrc, bpos,
                                                  N, E, nodeBlocks);

    alloc_kernel<<<(N + 1023) / 1024, 1024>>>(N);

    scatter_kernel<<<(E + 255) / 256, 256>>>(ei, E);

    aggregate_kernel<<<(N * 32 + 255) / 256, 256>>>(Wpos, bpos, N);

    mlp_kernel<<<(N + 63) / 64, 256>>>(W1, b1, W2, b2, out, N);
}

// round 14
// speedup vs baseline: 1.1017x; 1.0859x over previous
#include <cuda_runtime.h>
#include <cuda_fp16.h>

#define MAXN 100000
#define MAXE 800000

// ---- scratch (device globals; no runtime allocation allowed) ----
// g_svh: per node 128 halves, channel-interleaved: [a0,v0,a1,v1,...,a63,v63]
__device__ __align__(16) __half g_svh [MAXN * 128];
__device__ __align__(16) float  g_denom[MAXN * 64];   // self-loop seed (exp)
__device__ __align__(16) float  g_outh [MAXN * 64];
__device__ __align__(16) float4 g_pos4[MAXN];
__device__ int g_cnt [MAXN];      // in-degree (left ZERO by aggregate for next call)
__device__ int g_off [MAXN];      // segment starts (advanced to end by scatter)
__device__ int g_srcs[MAXE];      // src ids grouped by dst
__device__ int g_total;           // bump allocator (reset by proj block 0)

// ---- packed f32x2 helpers (sm_103a packed float pipe) ----
union F2U { float2 f; unsigned long long u; };
__device__ __forceinline__ float2 ffma2(float2 a, float2 b, float2 c) {
    F2U A, B, C, D; A.f = a; B.f = b; C.f = c;
    asm("fma.rn.f32x2 %0, %1, %2, %3;" : "=l"(D.u) : "l"(A.u), "l"(B.u), "l"(C.u));
    return D.f;
}
__device__ __forceinline__ float2 fadd2(float2 a, float2 b) {
    F2U A, B, D; A.f = a; B.f = b;
    asm("add.rn.f32x2 %0, %1, %2;" : "=l"(D.u) : "l"(A.u), "l"(B.u));
    return D.f;
}

// ---------------- proj (+ fused hist in extra blocks) ----------------
// __launch_bounds__(256, 4): cap regs at 62 so 4 blocks (32 warps) fit per SM
// (at 65 regs only 3 blocks fit; kernel is smem-latency bound at occ 34%).
__global__ void __launch_bounds__(256, 4) proj_kernel(
        const float* __restrict__ x,
        const float* __restrict__ pos,
        const int*   __restrict__ ei,
        const float* __restrict__ Wl,
        const float* __restrict__ Wsrc,
        const float* __restrict__ bpos,
        int N, int E, int nodeBlocks) {
    if ((int)blockIdx.x >= nodeBlocks) {
        int eb = blockIdx.x - nodeBlocks;
        int e0 = eb * 1024 + threadIdx.x;
#pragma unroll
        for (int k = 0; k < 4; k++) {
            int e = e0 + k * 256;
            if (e < E) atomicAdd(&g_cnt[ei[E + e]], 1);
        }
        return;
    }

    __shared__ float sWs[64 * 64];
    __shared__ float sWl[64 * 64];
    __shared__ float sx [64 * 68];

    int tid  = threadIdx.x;
    int base = blockIdx.x * 64;

    if (blockIdx.x == 0 && tid == 0) g_total = 0;
    if (tid < 64) {
        int node = base + tid;
        if (node < N)
            g_pos4[node] = make_float4(pos[node * 3 + 0], pos[node * 3 + 1],
                                       pos[node * 3 + 2], 0.f);
    }

    for (int g = tid; g < 4096; g += 256) {
        int h = g >> 10, k = (g >> 4) & 63, hd = g & 15;
        int o = h * 16 + hd;
        sWs[k * 64 + o] = Wsrc[g];
        sWl[k * 64 + o] = Wl[g];
    }
    for (int i = tid; i < 1024; i += 256) {
        int n = i >> 4, c4 = i & 15;
        int node = base + n;
        float4 xv = (node < N) ? *(const float4*)(x + (size_t)node * 64 + c4 * 4)
                               : make_float4(0.f, 0.f, 0.f, 0.f);
        int c = c4 * 4;
        sx[(c + 0) * 68 + n] = xv.x;
        sx[(c + 1) * 68 + n] = xv.y;
        sx[(c + 2) * 68 + n] = xv.z;
        sx[(c + 3) * 68 + n] = xv.w;
    }
    __syncthreads();

    int cg = tid & 15, ng = tid >> 4;
    float4 accS[4], accV[4];
#pragma unroll
    for (int i = 0; i < 4; i++) {
        accS[i] = make_float4(0.f, 0.f, 0.f, 0.f);
        accV[i] = make_float4(0.f, 0.f, 0.f, 0.f);
    }

#pragma unroll 8
    for (int k = 0; k < 64; k++) {
        float4 ws = *(float4*)(sWs + k * 64 + cg * 4);
        float4 wl = *(float4*)(sWl + k * 64 + cg * 4);
        float4 xa = *(float4*)(sx + k * 68 + ng * 4);
        float xv[4] = {xa.x, xa.y, xa.z, xa.w};
#pragma unroll
        for (int i = 0; i < 4; i++) {
            accS[i].x += xv[i] * ws.x;
            accS[i].y += xv[i] * ws.y;
            accS[i].z += xv[i] * ws.z;
            accS[i].w += xv[i] * ws.w;
            accV[i].x += xv[i] * wl.x;
            accV[i].y += xv[i] * wl.y;
            accV[i].z += xv[i] * wl.z;
            accV[i].w += xv[i] * wl.w;
        }
    }

    float4 b4 = *(const float4*)(bpos + cg * 4);

#pragma unroll
    for (int i = 0; i < 4; i++) {
        int node = base + ng * 4 + i;
        if (node < N) {
            uint4 o;
            *(__half2*)&o.x = __float22half2_rn(make_float2(accS[i].x, accV[i].x));
            *(__half2*)&o.y = __float22half2_rn(make_float2(accS[i].y, accV[i].y));
            *(__half2*)&o.z = __float22half2_rn(make_float2(accS[i].z, accV[i].z));
            *(__half2*)&o.w = __float22half2_rn(make_float2(accS[i].w, accV[i].w));
            *(uint4*)(g_svh + (size_t)node * 128 + cg * 8) = o;

            // self-loop seed: ex = exp(bpos - a_src); outh = ex*(v + bpos)
            float4 ex, m;
            ex.x = __expf(b4.x - accS[i].x);
            ex.y = __expf(b4.y - accS[i].y);
            ex.z = __expf(b4.z - accS[i].z);
            ex.w = __expf(b4.w - accS[i].w);
            m.x = ex.x * (accV[i].x + b4.x);
            m.y = ex.y * (accV[i].y + b4.y);
            m.z = ex.z * (accV[i].z + b4.z);
            m.w = ex.w * (accV[i].w + b4.w);
            *(float4*)(g_denom + (size_t)node * 64 + cg * 4) = ex;
            *(float4*)(g_outh  + (size_t)node * 64 + cg * 4) = m;
        }
    }
}

// ---------------- one-kernel segment allocation (atomic-bump scan) ----------
__global__ void alloc_kernel(int n) {
    __shared__ int ws[32];
    __shared__ int sbase;
    int i = blockIdx.x * 1024 + threadIdx.x;
    int v = (i < n) ? g_cnt[i] : 0;
    int lane = threadIdx.x & 31, w = threadIdx.x >> 5;
    int xi = v;
#pragma unroll
    for (int o = 1; o < 32; o <<= 1) {
        int t = __shfl_up_sync(~0u, xi, o);
        if (lane >= o) xi += t;
    }
    if (lane == 31) ws[w] = xi;
    __syncthreads();
    if (w == 0) {
        int y = ws[lane];
#pragma unroll
        for (int o = 1; o < 32; o <<= 1) {
            int t = __shfl_up_sync(~0u, y, o);
            if (lane >= o) y += t;
        }
        ws[lane] = y;
    }
    __syncthreads();
    if (threadIdx.x == 0) sbase = atomicAdd(&g_total, ws[31]);
    __syncthreads();
    if (i < n) g_off[i] = sbase + (w > 0 ? ws[w - 1] : 0) + xi - v;  // exclusive
}

__global__ void scatter_kernel(const int* __restrict__ ei, int E) {
    int e = blockIdx.x * 256 + threadIdx.x;
    if (e < E) {
        int d = ei[E + e];
        int idx = atomicAdd(&g_off[d], 1);   // g_off ends at segment end
        g_srcs[idx] = ei[e];
    }
}

// ---------------- aggregate: one warp per destination node (R11-exact) ------
// lane handles channels (2*lane, 2*lane+1).
__device__ __forceinline__ void edge_acc(
        const float4& pd, const float4& ps, uint2 u,
        const float2& wx, const float2& wy, const float2& wz, const float2& bb,
        float2& accD, float2& accM) {
    float rx = pd.x - ps.x, ry = pd.y - ps.y, rz = pd.z - ps.z;
    float2 dl = ffma2(make_float2(rx, rx), wx,
                ffma2(make_float2(ry, ry), wy,
                ffma2(make_float2(rz, rz), wz, bb)));
    float2 q0 = __half22float2(*(__half2*)&u.x);   // (a_c0, v_c0)
    float2 q1 = __half22float2(*(__half2*)&u.y);   // (a_c1, v_c1)
    float2 ex = make_float2(__expf(dl.x - q0.x), __expf(dl.y - q1.x));
    float2 vv = make_float2(q0.y, q1.y);
    accD = fadd2(accD, ex);
    accM = ffma2(ex, fadd2(vv, dl), accM);
}

__global__ void __launch_bounds__(256) aggregate_kernel(
        const float* __restrict__ Wpos,
        const float* __restrict__ bpos,
        int N) {
    int d    = (blockIdx.x * 256 + threadIdx.x) >> 5;
    int lane = threadIdx.x & 31;
    if (d >= N) return;

    int c0 = lane * 2;
    int h = c0 >> 4, hd = c0 & 15;
    float2 wx = *(const float2*)(Wpos + h * 48 + hd);
    float2 wy = *(const float2*)(Wpos + h * 48 + 16 + hd);
    float2 wz = *(const float2*)(Wpos + h * 48 + 32 + hd);
    float2 bb = *(const float2*)(bpos + h * 16 + hd);

    float4 pd = g_pos4[d];
    int end   = g_off[d];        // advanced to end by scatter
    int cnt   = g_cnt[d];
    int start = end - cnt;
    if (lane == 0) g_cnt[d] = 0;     // self-clean for the next call's histogram

    // seed with self-loop contribution written by proj
    float2 accD = *(float2*)(g_denom + (size_t)d * 64 + c0);
    float2 accM = *(float2*)(g_outh  + (size_t)d * 64 + c0);

    for (int base = 0; base < cnt; base += 32) {
        int m = cnt - base; if (m > 32) m = 32;
        int myS = (lane < m) ? g_srcs[start + base + lane] : 0;  // coalesced
        int j = 0;
        for (; j + 4 <= m; j += 4) {
            int s0 = __shfl_sync(~0u, myS, j + 0);
            int s1 = __shfl_sync(~0u, myS, j + 1);
            int s2 = __shfl_sync(~0u, myS, j + 2);
            int s3 = __shfl_sync(~0u, myS, j + 3);
            float4 p0 = g_pos4[s0];
            float4 p1 = g_pos4[s1];
            float4 p2 = g_pos4[s2];
            float4 p3 = g_pos4[s3];
            uint2 u0 = *(const uint2*)(g_svh + (size_t)s0 * 128 + c0 * 2);
            uint2 u1 = *(const uint2*)(g_svh + (size_t)s1 * 128 + c0 * 2);
            uint2 u2 = *(const uint2*)(g_svh + (size_t)s2 * 128 + c0 * 2);
            uint2 u3 = *(const uint2*)(g_svh + (size_t)s3 * 128 + c0 * 2);
            edge_acc(pd, p0, u0, wx, wy, wz, bb, accD, accM);
            edge_acc(pd, p1, u1, wx, wy, wz, bb, accD, accM);
            edge_acc(pd, p2, u2, wx, wy, wz, bb, accD, accM);
            edge_acc(pd, p3, u3, wx, wy, wz, bb, accD, accM);
        }
        for (; j < m; j++) {
            int s0 = __shfl_sync(~0u, myS, j);
            float4 p0 = g_pos4[s0];
            uint2 u0 = *(const uint2*)(g_svh + (size_t)s0 * 128 + c0 * 2);
            edge_acc(pd, p0, u0, wx, wy, wz, bb, accD, accM);
        }
    }

    *(float2*)(g_denom + (size_t)d * 64 + c0) = accD;
    *(float2*)(g_outh  + (size_t)d * 64 + c0) = accM;
}

// ---------------- MLP: t = outh/denom; y = relu(t@W1+b1)@W2+b2 --------------
__global__ void __launch_bounds__(256, 4) mlp_kernel(
        const float* __restrict__ W1,
        const float* __restrict__ b1,
        const float* __restrict__ W2,
        const float* __restrict__ b2,
        float* __restrict__ out, int N) {
    __shared__ float sW1[64 * 64];
    __shared__ float sW2[64 * 64];
    __shared__ float sx [64 * 68];
    int tid  = threadIdx.x;
    int base = blockIdx.x * 64;

    for (int g = tid; g < 4096; g += 256) { sW1[g] = W1[g]; sW2[g] = W2[g]; }

    for (int i = tid; i < 1024; i += 256) {
        int n = i >> 4, c4 = i & 15;
        int node = base + n;
        float4 o4 = make_float4(0.f, 0.f, 0.f, 0.f);
        float4 d4 = make_float4(1.f, 1.f, 1.f, 1.f);
        if (node < N) {
            o4 = ((const float4*)g_outh)[(size_t)node * 16 + c4];
            d4 = ((const float4*)g_denom)[(size_t)node * 16 + c4];
        }
        int c = c4 * 4;
        sx[(c + 0) * 68 + n] = o4.x / d4.x;
        sx[(c + 1) * 68 + n] = o4.y / d4.y;
        sx[(c + 2) * 68 + n] = o4.z / d4.z;
        sx[(c + 3) * 68 + n] = o4.w / d4.w;
    }
    __syncthreads();

    int cg = tid & 15, ng = tid >> 4;
    float4 bias = *(const float4*)(b1 + cg * 4);
    float4 acc[4];
#pragma unroll
    for (int i = 0; i < 4; i++) acc[i] = bias;

#pragma unroll 8
    for (int k = 0; k < 64; k++) {
        float4 w  = *(float4*)(sW1 + k * 64 + cg * 4);
        float4 xa = *(float4*)(sx + k * 68 + ng * 4);
        float xv[4] = {xa.x, xa.y, xa.z, xa.w};
#pragma unroll
        for (int i = 0; i < 4; i++) {
            acc[i].x += xv[i] * w.x;
            acc[i].y += xv[i] * w.y;
            acc[i].z += xv[i] * w.z;
            acc[i].w += xv[i] * w.w;
        }
    }
    __syncthreads();

#pragma unroll
    for (int i = 0; i < 4; i++) {
        int n = ng * 4 + i;
        sx[(cg * 4 + 0) * 68 + n] = fmaxf(acc[i].x, 0.f);
        sx[(cg * 4 + 1) * 68 + n] = fmaxf(acc[i].y, 0.f);
        sx[(cg * 4 + 2) * 68 + n] = fmaxf(acc[i].z, 0.f);
        sx[(cg * 4 + 3) * 68 + n] = fmaxf(acc[i].w, 0.f);
    }
    __syncthreads();

    float4 bias2 = *(const float4*)(b2 + cg * 4);
#pragma unroll
    for (int i = 0; i < 4; i++) acc[i] = bias2;

#pragma unroll 8
    for (int k = 0; k < 64; k++) {
        float4 w  = *(float4*)(sW2 + k * 64 + cg * 4);
        float4 xa = *(float4*)(sx + k * 68 + ng * 4);
        float xv[4] = {xa.x, xa.y, xa.z, xa.w};
#pragma unroll
        for (int i = 0; i < 4; i++) {
            acc[i].x += xv[i] * w.x;
            acc[i].y += xv[i] * w.y;
            acc[i].z += xv[i] * w.z;
            acc[i].w += xv[i] * w.w;
        }
    }
#pragma unroll
    for (int i = 0; i < 4; i++) {
        int node = base + ng * 4 + i;
        if (node < N)
            *(float4*)(out + (size_t)node * 64 + cg * 4) = acc[i];
    }
}

extern "C" void kernel_launch(void* const* d_in, const int* in_sizes, int n_in,
                              void* d_out, int out_size) {
    const float* x    = (const float*)d_in[0];
    const float* pos  = (const float*)d_in[1];
    const int*   ei   = (const int*)d_in[2];
    const float* Wl   = (const float*)d_in[3];
    const float* Wsrc = (const float*)d_in[4];
    // d_in[5] = W_dst  (unused: cancels exactly in the segment softmax)
    const float* Wpos = (const float*)d_in[6];
    const float* bpos = (const float*)d_in[7];
    const float* W1   = (const float*)d_in[8];
    const float* b1   = (const float*)d_in[9];
    const float* W2   = (const float*)d_in[10];
    const float* b2   = (const float*)d_in[11];
    float* out = (float*)d_out;

    int N  = in_sizes[0] / 64;
    int E  = in_sizes[2] / 2;

    int nodeBlocks = (N + 63) / 64;
    int histBlocks = (E + 1023) / 1024;
    proj_kernel<<<nodeBlocks + histBlocks, 256>>>(x, pos, ei, Wl, Wsrc, bpos,
                                                  N, E, nodeBlocks);

    alloc_kernel<<<(N + 1023) / 1024, 1024>>>(N);

    scatter_kernel<<<(E + 255) / 256, 256>>>(ei, E);

    aggregate_kernel<<<(N * 32 + 255) / 256, 256>>>(Wpos, bpos, N);

    mlp_kernel<<<(N + 63) / 64, 256>>>(W1, b1, W2, b2, out, N);
}

// round 16
// speedup vs baseline: 1.2616x; 1.1452x over previous
#include <cuda_runtime.h>
#include <cuda_fp16.h>
#include <cstdint>

typedef unsigned int u32;

#define MAXN 100000
#define MAXE 800000

// ---- scratch (device globals; no runtime allocation allowed) ----
// g_svh: per node 128 halves, channel-interleaved: [a0,v0,a1,v1,...,a63,v63]
__device__ __align__(16) __half g_svh [MAXN * 128];
__device__ __align__(16) float  g_denom[MAXN * 64];   // self-loop seed (exp)
__device__ __align__(16) float  g_outh [MAXN * 64];
__device__ __align__(16) float4 g_pos4[MAXN];
__device__ int g_cnt [MAXN];      // in-degree (left ZERO by aggregate for next call)
__device__ int g_off [MAXN];      // segment starts (advanced to end by scatter)
__device__ int g_srcs[MAXE];      // src ids grouped by dst
__device__ int g_total;           // bump allocator (reset by proj block 0)

// ---- packed f32x2 helpers (sm_103a packed float pipe) ----
union F2U { float2 f; unsigned long long u; };
__device__ __forceinline__ float2 ffma2(float2 a, float2 b, float2 c) {
    F2U A, B, C, D; A.f = a; B.f = b; C.f = c;
    asm("fma.rn.f32x2 %0, %1, %2, %3;" : "=l"(D.u) : "l"(A.u), "l"(B.u), "l"(C.u));
    return D.f;
}
__device__ __forceinline__ float2 fadd2(float2 a, float2 b) {
    F2U A, B, D; A.f = a; B.f = b;
    asm("add.rn.f32x2 %0, %1, %2;" : "=l"(D.u) : "l"(A.u), "l"(B.u));
    return D.f;
}

// ---- tensor-core helpers (legacy mma.sync path) ----
__device__ __forceinline__ u32 smem_u32(const void* p) {
    return (u32)__cvta_generic_to_shared(p);
}
__device__ __forceinline__ void ldsm_x4(u32& r0, u32& r1,
                                        u32& r2, u32& r3, u32 addr) {
    asm volatile("ldmatrix.sync.aligned.m8n8.x4.shared.b16 {%0,%1,%2,%3}, [%4];"
                 : "=r"(r0), "=r"(r1), "=r"(r2), "=r"(r3) : "r"(addr));
}
__device__ __forceinline__ void ldsm_x4_t(u32& r0, u32& r1,
                                          u32& r2, u32& r3, u32 addr) {
    asm volatile("ldmatrix.sync.aligned.m8n8.x4.trans.shared.b16 {%0,%1,%2,%3}, [%4];"
                 : "=r"(r0), "=r"(r1), "=r"(r2), "=r"(r3) : "r"(addr));
}
__device__ __forceinline__ void mma16816(float* c,
        u32 a0, u32 a1, u32 a2, u32 a3,
        u32 b0, u32 b1) {
    asm volatile(
        "mma.sync.aligned.m16n8k16.row.col.f32.f16.f16.f32 "
        "{%0,%1,%2,%3}, {%4,%5,%6,%7}, {%8,%9}, {%0,%1,%2,%3};"
        : "+f"(c[0]), "+f"(c[1]), "+f"(c[2]), "+f"(c[3])
        : "r"(a0), "r"(a1), "r"(a2), "r"(a3), "r"(b0), "r"(b1));
}

// ---------------- proj via HMMA (+ fused hist in extra blocks) ----------------
// node blocks: 128 nodes each. C[128 x 128] = Xfp16[128 x 64] @ [Wsrc|Wl]fp16[64 x 128].
// Warp w owns rows w*16..w*16+15, all 128 cols. acc[j] j<8 = a_src cols, j>=8 = v cols.
__global__ void __launch_bounds__(256) proj_kernel(
        const float* __restrict__ x,
        const float* __restrict__ pos,
        const int*   __restrict__ ei,
        const float* __restrict__ Wl,
        const float* __restrict__ Wsrc,
        const float* __restrict__ bpos,
        int N, int E, int nodeBlocks) {
    if ((int)blockIdx.x >= nodeBlocks) {
        int eb = blockIdx.x - nodeBlocks;
        int e0 = eb * 1024 + threadIdx.x;
#pragma unroll
        for (int k = 0; k < 4; k++) {
            int e = e0 + k * 256;
            if (e < E) atomicAdd(&g_cnt[ei[E + e]], 1);
        }
        return;
    }

    __shared__ __half sX[128 * 72];    // x tile fp16, stride 72 halves (144B % 128B = 16)
    __shared__ __half sW[64 * 136];    // [k][out 0..127], stride 136 halves (272B % 128B = 16)

    int tid  = threadIdx.x;
    int base = blockIdx.x * 128;

    if (blockIdx.x == 0 && tid == 0) g_total = 0;
    if (tid < 128) {
        int node = base + tid;
        if (node < N)
            g_pos4[node] = make_float4(pos[node * 3 + 0], pos[node * 3 + 1],
                                       pos[node * 3 + 2], 0.f);
    }

    // stage W: [H=4][K=64][HD=16] -> sW[k][h*16+hd] (Wsrc) / +64 (Wl), fp16
    {
        const float4* Ws4 = (const float4*)Wsrc;
        const float4* Wl4 = (const float4*)Wl;
        for (int i = tid; i < 1024; i += 256) {
            int e0 = i * 4;
            int h = e0 >> 10, k = (e0 >> 4) & 63, hd0 = e0 & 15;
            float4 fs = Ws4[i];
            float4 fl = Wl4[i];
            uint2 us, ul;
            *(__half2*)&us.x = __floats2half2_rn(fs.x, fs.y);
            *(__half2*)&us.y = __floats2half2_rn(fs.z, fs.w);
            *(__half2*)&ul.x = __floats2half2_rn(fl.x, fl.y);
            *(__half2*)&ul.y = __floats2half2_rn(fl.z, fl.w);
            *(uint2*)(sW + k * 136 + h * 16 + hd0)      = us;
            *(uint2*)(sW + k * 136 + 64 + h * 16 + hd0) = ul;
        }
    }
    // stage X tile fp16 (zeros for padding rows)
    for (int i = tid; i < 2048; i += 256) {
        int n = i >> 4, c4 = i & 15;
        int node = base + n;
        float4 xv = (node < N) ? *(const float4*)(x + (size_t)node * 64 + c4 * 4)
                               : make_float4(0.f, 0.f, 0.f, 0.f);
        uint2 u;
        *(__half2*)&u.x = __floats2half2_rn(xv.x, xv.y);
        *(__half2*)&u.y = __floats2half2_rn(xv.z, xv.w);
        *(uint2*)(sX + n * 72 + c4 * 4) = u;
    }
    __syncthreads();

    int lane = tid & 31, w = tid >> 5;
    u32 sXu = smem_u32(sX);
    u32 sWu = smem_u32(sW);
    // A addr: row = w*16 + (lane&15), k-col = ks*16 + (lane>>4)*8
    u32 aAddr = sXu + ((w * 16 + (lane & 15)) * 72 + (lane >> 4) * 8) * 2;
    // B addr: row(k) = ks*16 + (lane&15), col = jp*16 + (lane>>4)*8
    u32 bAddr = sWu + ((lane & 15) * 136 + (lane >> 4) * 8) * 2;

    float acc[16][4];
#pragma unroll
    for (int j = 0; j < 16; j++) {
        acc[j][0] = 0.f; acc[j][1] = 0.f; acc[j][2] = 0.f; acc[j][3] = 0.f;
    }

#pragma unroll
    for (int ks = 0; ks < 4; ks++) {
        u32 a0, a1, a2, a3;
        ldsm_x4(a0, a1, a2, a3, aAddr + ks * 32);
#pragma unroll
        for (int jp = 0; jp < 8; jp++) {
            u32 b0, b1, b2, b3;
            ldsm_x4_t(b0, b1, b2, b3, bAddr + ks * (16 * 136 * 2) + jp * 32);
            mma16816(acc[2 * jp],     a0, a1, a2, a3, b0, b1);
            mma16816(acc[2 * jp + 1], a0, a1, a2, a3, b2, b3);
        }
    }

    // epilogue: acc[j] = a_src channels j*8.., acc[j+8] = v channels j*8..
    // thread holds (r0, ch),(r0, ch+1) in c[0],c[1] and (r0+8, ·) in c[2],c[3]
    int r0 = base + w * 16 + (lane >> 2);
    int r1 = r0 + 8;
#pragma unroll
    for (int j = 0; j < 8; j++) {
        int ch = j * 8 + (lane & 3) * 2;
        float2 bp = *(const float2*)(bpos + ch);
        if (r0 < N) {
            float S0 = acc[j][0], S1 = acc[j][1];
            float V0 = acc[j + 8][0], V1 = acc[j + 8][1];
            uint2 sv;
            *(__half2*)&sv.x = __floats2half2_rn(S0, V0);
            *(__half2*)&sv.y = __floats2half2_rn(S1, V1);
            *(uint2*)(g_svh + (size_t)r0 * 128 + ch * 2) = sv;
            float e0 = __expf(bp.x - S0), e1 = __expf(bp.y - S1);
            *(float2*)(g_denom + (size_t)r0 * 64 + ch) = make_float2(e0, e1);
            *(float2*)(g_outh  + (size_t)r0 * 64 + ch) =
                make_float2(e0 * (V0 + bp.x), e1 * (V1 + bp.y));
        }
        if (r1 < N) {
            float S0 = acc[j][2], S1 = acc[j][3];
            float V0 = acc[j + 8][2], V1 = acc[j + 8][3];
            uint2 sv;
            *(__half2*)&sv.x = __floats2half2_rn(S0, V0);
            *(__half2*)&sv.y = __floats2half2_rn(S1, V1);
            *(uint2*)(g_svh + (size_t)r1 * 128 + ch * 2) = sv;
            float e0 = __expf(bp.x - S0), e1 = __expf(bp.y - S1);
            *(float2*)(g_denom + (size_t)r1 * 64 + ch) = make_float2(e0, e1);
            *(float2*)(g_outh  + (size_t)r1 * 64 + ch) =
                make_float2(e0 * (V0 + bp.x), e1 * (V1 + bp.y));
        }
    }
}

// ---------------- one-kernel segment allocation (atomic-bump scan) ----------
__global__ void alloc_kernel(int n) {
    __shared__ int ws[32];
    __shared__ int sbase;
    int i = blockIdx.x * 1024 + threadIdx.x;
    int v = (i < n) ? g_cnt[i] : 0;
    int lane = threadIdx.x & 31, w = threadIdx.x >> 5;
    int xi = v;
#pragma unroll
    for (int o = 1; o < 32; o <<= 1) {
        int t = __shfl_up_sync(~0u, xi, o);
        if (lane >= o) xi += t;
    }
    if (lane == 31) ws[w] = xi;
    __syncthreads();
    if (w == 0) {
        int y = ws[lane];
#pragma unroll
        for (int o = 1; o < 32; o <<= 1) {
            int t = __shfl_up_sync(~0u, y, o);
            if (lane >= o) y += t;
        }
        ws[lane] = y;
    }
    __syncthreads();
    if (threadIdx.x == 0) sbase = atomicAdd(&g_total, ws[31]);
    __syncthreads();
    if (i < n) g_off[i] = sbase + (w > 0 ? ws[w - 1] : 0) + xi - v;  // exclusive
}

__global__ void scatter_kernel(const int* __restrict__ ei, int E) {
    int e = blockIdx.x * 256 + threadIdx.x;
    if (e < E) {
        int d = ei[E + e];
        int idx = atomicAdd(&g_off[d], 1);   // g_off ends at segment end
        g_srcs[idx] = ei[e];
    }
}

// ---------------- aggregate: one warp per destination node (R11-exact) ------
// lane handles channels (2*lane, 2*lane+1).
__device__ __forceinline__ void edge_acc(
        const float4& pd, const float4& ps, uint2 u,
        const float2& wx, const float2& wy, const float2& wz, const float2& bb,
        float2& accD, float2& accM) {
    float rx = pd.x - ps.x, ry = pd.y - ps.y, rz = pd.z - ps.z;
    float2 dl = ffma2(make_float2(rx, rx), wx,
                ffma2(make_float2(ry, ry), wy,
                ffma2(make_float2(rz, rz), wz, bb)));
    float2 q0 = __half22float2(*(__half2*)&u.x);   // (a_c0, v_c0)
    float2 q1 = __half22float2(*(__half2*)&u.y);   // (a_c1, v_c1)
    float2 ex = make_float2(__expf(dl.x - q0.x), __expf(dl.y - q1.x));
    float2 vv = make_float2(q0.y, q1.y);
    accD = fadd2(accD, ex);
    accM = ffma2(ex, fadd2(vv, dl), accM);
}

__global__ void __launch_bounds__(256) aggregate_kernel(
        const float* __restrict__ Wpos,
        const float* __restrict__ bpos,
        int N) {
    int d    = (blockIdx.x * 256 + threadIdx.x) >> 5;
    int lane = threadIdx.x & 31;
    if (d >= N) return;

    int c0 = lane * 2;
    int h = c0 >> 4, hd = c0 & 15;
    float2 wx = *(const float2*)(Wpos + h * 48 + hd);
    float2 wy = *(const float2*)(Wpos + h * 48 + 16 + hd);
    float2 wz = *(const float2*)(Wpos + h * 48 + 32 + hd);
    float2 bb = *(const float2*)(bpos + h * 16 + hd);

    float4 pd = g_pos4[d];
    int end   = g_off[d];        // advanced to end by scatter
    int cnt   = g_cnt[d];
    int start = end - cnt;
    if (lane == 0) g_cnt[d] = 0;     // self-clean for the next call's histogram

    // seed with self-loop contribution written by proj
    float2 accD = *(float2*)(g_denom + (size_t)d * 64 + c0);
    float2 accM = *(float2*)(g_outh  + (size_t)d * 64 + c0);

    for (int base = 0; base < cnt; base += 32) {
        int m = cnt - base; if (m > 32) m = 32;
        int myS = (lane < m) ? g_srcs[start + base + lane] : 0;  // coalesced
        int j = 0;
        for (; j + 4 <= m; j += 4) {
            int s0 = __shfl_sync(~0u, myS, j + 0);
            int s1 = __shfl_sync(~0u, myS, j + 1);
            int s2 = __shfl_sync(~0u, myS, j + 2);
            int s3 = __shfl_sync(~0u, myS, j + 3);
            float4 p0 = g_pos4[s0];
            float4 p1 = g_pos4[s1];
            float4 p2 = g_pos4[s2];
            float4 p3 = g_pos4[s3];
            uint2 u0 = *(const uint2*)(g_svh + (size_t)s0 * 128 + c0 * 2);
            uint2 u1 = *(const uint2*)(g_svh + (size_t)s1 * 128 + c0 * 2);
            uint2 u2 = *(const uint2*)(g_svh + (size_t)s2 * 128 + c0 * 2);
            uint2 u3 = *(const uint2*)(g_svh + (size_t)s3 * 128 + c0 * 2);
            edge_acc(pd, p0, u0, wx, wy, wz, bb, accD, accM);
            edge_acc(pd, p1, u1, wx, wy, wz, bb, accD, accM);
            edge_acc(pd, p2, u2, wx, wy, wz, bb, accD, accM);
            edge_acc(pd, p3, u3, wx, wy, wz, bb, accD, accM);
        }
        for (; j < m; j++) {
            int s0 = __shfl_sync(~0u, myS, j);
            float4 p0 = g_pos4[s0];
            uint2 u0 = *(const uint2*)(g_svh + (size_t)s0 * 128 + c0 * 2);
            edge_acc(pd, p0, u0, wx, wy, wz, bb, accD, accM);
        }
    }

    *(float2*)(g_denom + (size_t)d * 64 + c0) = accD;
    *(float2*)(g_outh  + (size_t)d * 64 + c0) = accM;
}

// ---------------- MLP: t = outh/denom; y = relu(t@W1+b1)@W2+b2 --------------
__global__ void __launch_bounds__(256, 4) mlp_kernel(
        const float* __restrict__ W1,
        const float* __restrict__ b1,
        const float* __restrict__ W2,
        const float* __restrict__ b2,
        float* __restrict__ out, int N) {
    __shared__ float sW1[64 * 64];
    __shared__ float sW2[64 * 64];
    __shared__ float sx [64 * 68];
    int tid  = threadIdx.x;
    int base = blockIdx.x * 64;

    for (int g = tid; g < 4096; g += 256) { sW1[g] = W1[g]; sW2[g] = W2[g]; }

    for (int i = tid; i < 1024; i += 256) {
        int n = i >> 4, c4 = i & 15;
        int node = base + n;
        float4 o4 = make_float4(0.f, 0.f, 0.f, 0.f);
        float4 d4 = make_float4(1.f, 1.f, 1.f, 1.f);
        if (node < N) {
            o4 = ((const float4*)g_outh)[(size_t)node * 16 + c4];
            d4 = ((const float4*)g_denom)[(size_t)node * 16 + c4];
        }
        int c = c4 * 4;
        sx[(c + 0) * 68 + n] = o4.x / d4.x;
        sx[(c + 1) * 68 + n] = o4.y / d4.y;
        sx[(c + 2) * 68 + n] = o4.z / d4.z;
        sx[(c + 3) * 68 + n] = o4.w / d4.w;
    }
    __syncthreads();

    int cg = tid & 15, ng = tid >> 4;
    float4 bias = *(const float4*)(b1 + cg * 4);
    float4 acc[4];
#pragma unroll
    for (int i = 0; i < 4; i++) acc[i] = bias;

#pragma unroll 8
    for (int k = 0; k < 64; k++) {
        float4 w  = *(float4*)(sW1 + k * 64 + cg * 4);
        float4 xa = *(float4*)(sx + k * 68 + ng * 4);
        float xv[4] = {xa.x, xa.y, xa.z, xa.w};
#pragma unroll
        for (int i = 0; i < 4; i++) {
            acc[i].x += xv[i] * w.x;
            acc[i].y += xv[i] * w.y;
            acc[i].z += xv[i] * w.z;
            acc[i].w += xv[i] * w.w;
        }
    }
    __syncthreads();

#pragma unroll
    for (int i = 0; i < 4; i++) {
        int n = ng * 4 + i;
        sx[(cg * 4 + 0) * 68 + n] = fmaxf(acc[i].x, 0.f);
        sx[(cg * 4 + 1) * 68 + n] = fmaxf(acc[i].y, 0.f);
        sx[(cg * 4 + 2) * 68 + n] = fmaxf(acc[i].z, 0.f);
        sx[(cg * 4 + 3) * 68 + n] = fmaxf(acc[i].w, 0.f);
    }
    __syncthreads();

    float4 bias2 = *(const float4*)(b2 + cg * 4);
#pragma unroll
    for (int i = 0; i < 4; i++) acc[i] = bias2;

#pragma unroll 8
    for (int k = 0; k < 64; k++) {
        float4 w  = *(float4*)(sW2 + k * 64 + cg * 4);
        float4 xa = *(float4*)(sx + k * 68 + ng * 4);
        float xv[4] = {xa.x, xa.y, xa.z, xa.w};
#pragma unroll
        for (int i = 0; i < 4; i++) {
            acc[i].x += xv[i] * w.x;
            acc[i].y += xv[i] * w.y;
            acc[i].z += xv[i] * w.z;
            acc[i].w += xv[i] * w.w;
        }
    }
#pragma unroll
    for (int i = 0; i < 4; i++) {
        int node = base + ng * 4 + i;
        if (node < N)
            *(float4*)(out + (size_t)node * 64 + cg * 4) = acc[i];
    }
}

extern "C" void kernel_launch(void* const* d_in, const int* in_sizes, int n_in,
                              void* d_out, int out_size) {
    const float* x    = (const float*)d_in[0];
    const float* pos  = (const float*)d_in[1];
    const int*   ei   = (const int*)d_in[2];
    const float* Wl   = (const float*)d_in[3];
    const float* Wsrc = (const float*)d_in[4];
    // d_in[5] = W_dst  (unused: cancels exactly in the segment softmax)
    const float* Wpos = (const float*)d_in[6];
    const float* bpos = (const float*)d_in[7];
    const float* W1   = (const float*)d_in[8];
    const float* b1   = (const float*)d_in[9];
    const float* W2   = (const float*)d_in[10];
    const float* b2   = (const float*)d_in[11];
    float* out = (float*)d_out;

    int N  = in_sizes[0] / 64;
    int E  = in_sizes[2] / 2;

    int nodeBlocks = (N + 127) / 128;
    int histBlocks = (E + 1023) / 1024;
    proj_kernel<<<nodeBlocks + histBlocks, 256>>>(x, pos, ei, Wl, Wsrc, bpos,
                                                  N, E, nodeBlocks);

    alloc_kernel<<<(N + 1023) / 1024, 1024>>>(N);

    scatter_kernel<<<(E + 255) / 256, 256>>>(ei, E);

    aggregate_kernel<<<(N * 32 + 255) / 256, 256>>>(Wpos, bpos, N);

    mlp_kernel<<<(N + 63) / 64, 256>>>(W1, b1, W2, b2, out, N);
}

// round 17
// speedup vs baseline: 1.6356x; 1.2965x over previous
#include <cuda_runtime.h>
#include <cuda_fp16.h>
#include <cstdint>

typedef unsigned int u32;

#define MAXN 100000
#define MAXE 800000

// ---- scratch (device globals; no runtime allocation allowed) ----
// g_svh: per node 128 halves, channel-interleaved: [a0,v0,a1,v1,...,a63,v63]
__device__ __align__(16) __half g_svh [MAXN * 128];
__device__ __align__(16) float  g_denom[MAXN * 64];   // self-loop seed (exp)
__device__ __align__(16) float  g_outh [MAXN * 64];
__device__ __align__(16) float4 g_pos4[MAXN];
__device__ int g_cnt [MAXN];      // in-degree (left ZERO by aggregate for next call)
__device__ int g_off [MAXN];      // segment starts (advanced to end by scatter)
__device__ int g_srcs[MAXE];      // src ids grouped by dst
__device__ int g_total;           // bump allocator (reset by proj block 0)

// ---- packed f32x2 helpers (sm_103a packed float pipe) ----
union F2U { float2 f; unsigned long long u; };
__device__ __forceinline__ float2 ffma2(float2 a, float2 b, float2 c) {
    F2U A, B, C, D; A.f = a; B.f = b; C.f = c;
    asm("fma.rn.f32x2 %0, %1, %2, %3;" : "=l"(D.u) : "l"(A.u), "l"(B.u), "l"(C.u));
    return D.f;
}
__device__ __forceinline__ float2 fadd2(float2 a, float2 b) {
    F2U A, B, D; A.f = a; B.f = b;
    asm("add.rn.f32x2 %0, %1, %2;" : "=l"(D.u) : "l"(A.u), "l"(B.u));
    return D.f;
}

// ---- tensor-core helpers (legacy mma.sync path) ----
__device__ __forceinline__ u32 smem_u32(const void* p) {
    return (u32)__cvta_generic_to_shared(p);
}
__device__ __forceinline__ void ldsm_x4(u32& r0, u32& r1,
                                        u32& r2, u32& r3, u32 addr) {
    asm volatile("ldmatrix.sync.aligned.m8n8.x4.shared.b16 {%0,%1,%2,%3}, [%4];"
                 : "=r"(r0), "=r"(r1), "=r"(r2), "=r"(r3) : "r"(addr));
}
__device__ __forceinline__ void ldsm_x4_t(u32& r0, u32& r1,
                                          u32& r2, u32& r3, u32 addr) {
    asm volatile("ldmatrix.sync.aligned.m8n8.x4.trans.shared.b16 {%0,%1,%2,%3}, [%4];"
                 : "=r"(r0), "=r"(r1), "=r"(r2), "=r"(r3) : "r"(addr));
}
__device__ __forceinline__ void mma16816(float* c,
        u32 a0, u32 a1, u32 a2, u32 a3,
        u32 b0, u32 b1) {
    asm volatile(
        "mma.sync.aligned.m16n8k16.row.col.f32.f16.f16.f32 "
        "{%0,%1,%2,%3}, {%4,%5,%6,%7}, {%8,%9}, {%0,%1,%2,%3};"
        : "+f"(c[0]), "+f"(c[1]), "+f"(c[2]), "+f"(c[3])
        : "r"(a0), "r"(a1), "r"(a2), "r"(a3), "r"(b0), "r"(b1));
}

// ---------------- proj via HMMA (+ fused hist in extra blocks) ----------------
// node blocks: 128 nodes each. C[128 x 128] = Xfp16[128 x 64] @ [Wsrc|Wl]fp16[64 x 128].
// Warp w owns rows w*16..w*16+15, all 128 cols. acc[j] j<8 = a_src cols, j>=8 = v cols.
__global__ void __launch_bounds__(256) proj_kernel(
        const float* __restrict__ x,
        const float* __restrict__ pos,
        const int*   __restrict__ ei,
        const float* __restrict__ Wl,
        const float* __restrict__ Wsrc,
        const float* __restrict__ bpos,
        int N, int E, int nodeBlocks) {
    if ((int)blockIdx.x >= nodeBlocks) {
        int eb = blockIdx.x - nodeBlocks;
        int e0 = eb * 1024 + threadIdx.x;
#pragma unroll
        for (int k = 0; k < 4; k++) {
            int e = e0 + k * 256;
            if (e < E) atomicAdd(&g_cnt[ei[E + e]], 1);
        }
        return;
    }

    __shared__ __half sX[128 * 72];    // x tile fp16, stride 72 halves (144B % 128B = 16)
    __shared__ __half sW[64 * 136];    // [k][out 0..127], stride 136 halves (272B % 128B = 16)

    int tid  = threadIdx.x;
    int base = blockIdx.x * 128;

    if (blockIdx.x == 0 && tid == 0) g_total = 0;
    if (tid < 128) {
        int node = base + tid;
        if (node < N)
            g_pos4[node] = make_float4(pos[node * 3 + 0], pos[node * 3 + 1],
                                       pos[node * 3 + 2], 0.f);
    }

    // stage W: [H=4][K=64][HD=16] -> sW[k][h*16+hd] (Wsrc) / +64 (Wl), fp16
    {
        const float4* Ws4 = (const float4*)Wsrc;
        const float4* Wl4 = (const float4*)Wl;
        for (int i = tid; i < 1024; i += 256) {
            int e0 = i * 4;
            int h = e0 >> 10, k = (e0 >> 4) & 63, hd0 = e0 & 15;
            float4 fs = Ws4[i];
            float4 fl = Wl4[i];
            uint2 us, ul;
            *(__half2*)&us.x = __floats2half2_rn(fs.x, fs.y);
            *(__half2*)&us.y = __floats2half2_rn(fs.z, fs.w);
            *(__half2*)&ul.x = __floats2half2_rn(fl.x, fl.y);
            *(__half2*)&ul.y = __floats2half2_rn(fl.z, fl.w);
            *(uint2*)(sW + k * 136 + h * 16 + hd0)      = us;
            *(uint2*)(sW + k * 136 + 64 + h * 16 + hd0) = ul;
        }
    }
    // stage X tile fp16 (zeros for padding rows)
    for (int i = tid; i < 2048; i += 256) {
        int n = i >> 4, c4 = i & 15;
        int node = base + n;
        float4 xv = (node < N) ? *(const float4*)(x + (size_t)node * 64 + c4 * 4)
                               : make_float4(0.f, 0.f, 0.f, 0.f);
        uint2 u;
        *(__half2*)&u.x = __floats2half2_rn(xv.x, xv.y);
        *(__half2*)&u.y = __floats2half2_rn(xv.z, xv.w);
        *(uint2*)(sX + n * 72 + c4 * 4) = u;
    }
    __syncthreads();

    int lane = tid & 31, w = tid >> 5;
    u32 sXu = smem_u32(sX);
    u32 sWu = smem_u32(sW);
    // A addr: row = w*16 + (lane&15), k-col = ks*16 + (lane>>4)*8
    u32 aAddr = sXu + ((w * 16 + (lane & 15)) * 72 + (lane >> 4) * 8) * 2;
    // B addr: row(k) = ks*16 + (lane&15), col = jp*16 + (lane>>4)*8
    u32 bAddr = sWu + ((lane & 15) * 136 + (lane >> 4) * 8) * 2;

    float acc[16][4];
#pragma unroll
    for (int j = 0; j < 16; j++) {
        acc[j][0] = 0.f; acc[j][1] = 0.f; acc[j][2] = 0.f; acc[j][3] = 0.f;
    }

#pragma unroll
    for (int ks = 0; ks < 4; ks++) {
        u32 a0, a1, a2, a3;
        ldsm_x4(a0, a1, a2, a3, aAddr + ks * 32);
#pragma unroll
        for (int jp = 0; jp < 8; jp++) {
            u32 b0, b1, b2, b3;
            ldsm_x4_t(b0, b1, b2, b3, bAddr + ks * (16 * 136 * 2) + jp * 32);
            mma16816(acc[2 * jp],     a0, a1, a2, a3, b0, b1);
            mma16816(acc[2 * jp + 1], a0, a1, a2, a3, b2, b3);
        }
    }

    // epilogue: acc[j] = a_src channels j*8.., acc[j+8] = v channels j*8..
    // thread holds (r0, ch),(r0, ch+1) in c[0],c[1] and (r0+8, ·) in c[2],c[3]
    int r0 = base + w * 16 + (lane >> 2);
    int r1 = r0 + 8;
#pragma unroll
    for (int j = 0; j < 8; j++) {
        int ch = j * 8 + (lane & 3) * 2;
        float2 bp = *(const float2*)(bpos + ch);
        if (r0 < N) {
            float S0 = acc[j][0], S1 = acc[j][1];
            float V0 = acc[j + 8][0], V1 = acc[j + 8][1];
            uint2 sv;
            *(__half2*)&sv.x = __floats2half2_rn(S0, V0);
            *(__half2*)&sv.y = __floats2half2_rn(S1, V1);
            *(uint2*)(g_svh + (size_t)r0 * 128 + ch * 2) = sv;
            float e0 = __expf(bp.x - S0), e1 = __expf(bp.y - S1);
            *(float2*)(g_denom + (size_t)r0 * 64 + ch) = make_float2(e0, e1);
            *(float2*)(g_outh  + (size_t)r0 * 64 + ch) =
                make_float2(e0 * (V0 + bp.x), e1 * (V1 + bp.y));
        }
        if (r1 < N) {
            float S0 = acc[j][2], S1 = acc[j][3];
            float V0 = acc[j + 8][2], V1 = acc[j + 8][3];
            uint2 sv;
            *(__half2*)&sv.x = __floats2half2_rn(S0, V0);
            *(__half2*)&sv.y = __floats2half2_rn(S1, V1);
            *(uint2*)(g_svh + (size_t)r1 * 128 + ch * 2) = sv;
            float e0 = __expf(bp.x - S0), e1 = __expf(bp.y - S1);
            *(float2*)(g_denom + (size_t)r1 * 64 + ch) = make_float2(e0, e1);
            *(float2*)(g_outh  + (size_t)r1 * 64 + ch) =
                make_float2(e0 * (V0 + bp.x), e1 * (V1 + bp.y));
        }
    }
}

// ---------------- one-kernel segment allocation (atomic-bump scan) ----------
__global__ void alloc_kernel(int n) {
    __shared__ int ws[32];
    __shared__ int sbase;
    int i = blockIdx.x * 1024 + threadIdx.x;
    int v = (i < n) ? g_cnt[i] : 0;
    int lane = threadIdx.x & 31, w = threadIdx.x >> 5;
    int xi = v;
#pragma unroll
    for (int o = 1; o < 32; o <<= 1) {
        int t = __shfl_up_sync(~0u, xi, o);
        if (lane >= o) xi += t;
    }
    if (lane == 31) ws[w] = xi;
    __syncthreads();
    if (w == 0) {
        int y = ws[lane];
#pragma unroll
        for (int o = 1; o < 32; o <<= 1) {
            int t = __shfl_up_sync(~0u, y, o);
            if (lane >= o) y += t;
        }
        ws[lane] = y;
    }
    __syncthreads();
    if (threadIdx.x == 0) sbase = atomicAdd(&g_total, ws[31]);
    __syncthreads();
    if (i < n) g_off[i] = sbase + (w > 0 ? ws[w - 1] : 0) + xi - v;  // exclusive
}

__global__ void scatter_kernel(const int* __restrict__ ei, int E) {
    int e = blockIdx.x * 256 + threadIdx.x;
    if (e < E) {
        int d = ei[E + e];
        int idx = atomicAdd(&g_off[d], 1);   // g_off ends at segment end
        g_srcs[idx] = ei[e];
    }
}

// ---------------- aggregate: one warp per destination node (R11-exact) ------
// lane handles channels (2*lane, 2*lane+1).
__device__ __forceinline__ void edge_acc(
        const float4& pd, const float4& ps, uint2 u,
        const float2& wx, const float2& wy, const float2& wz, const float2& bb,
        float2& accD, float2& accM) {
    float rx = pd.x - ps.x, ry = pd.y - ps.y, rz = pd.z - ps.z;
    float2 dl = ffma2(make_float2(rx, rx), wx,
                ffma2(make_float2(ry, ry), wy,
                ffma2(make_float2(rz, rz), wz, bb)));
    float2 q0 = __half22float2(*(__half2*)&u.x);   // (a_c0, v_c0)
    float2 q1 = __half22float2(*(__half2*)&u.y);   // (a_c1, v_c1)
    float2 ex = make_float2(__expf(dl.x - q0.x), __expf(dl.y - q1.x));
    float2 vv = make_float2(q0.y, q1.y);
    accD = fadd2(accD, ex);
    accM = ffma2(ex, fadd2(vv, dl), accM);
}

__global__ void __launch_bounds__(256) aggregate_kernel(
        const float* __restrict__ Wpos,
        const float* __restrict__ bpos,
        int N) {
    int d    = (blockIdx.x * 256 + threadIdx.x) >> 5;
    int lane = threadIdx.x & 31;
    if (d >= N) return;

    int c0 = lane * 2;
    int h = c0 >> 4, hd = c0 & 15;
    float2 wx = *(const float2*)(Wpos + h * 48 + hd);
    float2 wy = *(const float2*)(Wpos + h * 48 + 16 + hd);
    float2 wz = *(const float2*)(Wpos + h * 48 + 32 + hd);
    float2 bb = *(const float2*)(bpos + h * 16 + hd);

    float4 pd = g_pos4[d];
    int end   = g_off[d];        // advanced to end by scatter
    int cnt   = g_cnt[d];
    int start = end - cnt;
    if (lane == 0) g_cnt[d] = 0;     // self-clean for the next call's histogram

    // seed with self-loop contribution written by proj
    float2 accD = *(float2*)(g_denom + (size_t)d * 64 + c0);
    float2 accM = *(float2*)(g_outh  + (size_t)d * 64 + c0);

    for (int base = 0; base < cnt; base += 32) {
        int m = cnt - base; if (m > 32) m = 32;
        int myS = (lane < m) ? g_srcs[start + base + lane] : 0;  // coalesced
        int j = 0;
        for (; j + 4 <= m; j += 4) {
            int s0 = __shfl_sync(~0u, myS, j + 0);
            int s1 = __shfl_sync(~0u, myS, j + 1);
            int s2 = __shfl_sync(~0u, myS, j + 2);
            int s3 = __shfl_sync(~0u, myS, j + 3);
            float4 p0 = g_pos4[s0];
            float4 p1 = g_pos4[s1];
            float4 p2 = g_pos4[s2];
            float4 p3 = g_pos4[s3];
            uint2 u0 = *(const uint2*)(g_svh + (size_t)s0 * 128 + c0 * 2);
            uint2 u1 = *(const uint2*)(g_svh + (size_t)s1 * 128 + c0 * 2);
            uint2 u2 = *(const uint2*)(g_svh + (size_t)s2 * 128 + c0 * 2);
            uint2 u3 = *(const uint2*)(g_svh + (size_t)s3 * 128 + c0 * 2);
            edge_acc(pd, p0, u0, wx, wy, wz, bb, accD, accM);
            edge_acc(pd, p1, u1, wx, wy, wz, bb, accD, accM);
            edge_acc(pd, p2, u2, wx, wy, wz, bb, accD, accM);
            edge_acc(pd, p3, u3, wx, wy, wz, bb, accD, accM);
        }
        for (; j < m; j++) {
            int s0 = __shfl_sync(~0u, myS, j);
            float4 p0 = g_pos4[s0];
            uint2 u0 = *(const uint2*)(g_svh + (size_t)s0 * 128 + c0 * 2);
            edge_acc(pd, p0, u0, wx, wy, wz, bb, accD, accM);
        }
    }

    *(float2*)(g_denom + (size_t)d * 64 + c0) = accD;
    *(float2*)(g_outh  + (size_t)d * 64 + c0) = accM;
}

// ---------------- MLP via HMMA: t = outh/denom; y = relu(t@W1+b1)@W2+b2 -----
// 128-node tiles, 8 warps; warp owns rows w*16..+15, cols 0..63.
__global__ void __launch_bounds__(256) mlp_kernel(
        const float* __restrict__ W1,
        const float* __restrict__ b1,
        const float* __restrict__ W2,
        const float* __restrict__ b2,
        float* __restrict__ out, int N) {
    __shared__ __half sW1[64 * 72];   // [k][o], stride 72 halves (144B % 128B = 16)
    __shared__ __half sW2[64 * 72];
    __shared__ __half sT [128 * 72];  // t / h tile fp16

    int tid  = threadIdx.x;
    int base = blockIdx.x * 128;

    // stage W1, W2 fp16 (row-major [k][o], k = in, o = out)
    {
        const float4* W14 = (const float4*)W1;
        const float4* W24 = (const float4*)W2;
        for (int i = tid; i < 1024; i += 256) {
            int e0 = i * 4;
            int k = e0 >> 6, o = e0 & 63;
            float4 f1 = W14[i];
            float4 f2 = W24[i];
            uint2 u1, u2;
            *(__half2*)&u1.x = __floats2half2_rn(f1.x, f1.y);
            *(__half2*)&u1.y = __floats2half2_rn(f1.z, f1.w);
            *(__half2*)&u2.x = __floats2half2_rn(f2.x, f2.y);
            *(__half2*)&u2.y = __floats2half2_rn(f2.z, f2.w);
            *(uint2*)(sW1 + k * 72 + o) = u1;
            *(uint2*)(sW2 + k * 72 + o) = u2;
        }
    }
    // stage t = outh/denom as fp16
    for (int i = tid; i < 2048; i += 256) {
        int n = i >> 4, c4 = i & 15;
        int node = base + n;
        float4 o4 = make_float4(0.f, 0.f, 0.f, 0.f);
        float4 d4 = make_float4(1.f, 1.f, 1.f, 1.f);
        if (node < N) {
            o4 = ((const float4*)g_outh)[(size_t)node * 16 + c4];
            d4 = ((const float4*)g_denom)[(size_t)node * 16 + c4];
        }
        uint2 u;
        *(__half2*)&u.x = __floats2half2_rn(o4.x / d4.x, o4.y / d4.y);
        *(__half2*)&u.y = __floats2half2_rn(o4.z / d4.z, o4.w / d4.w);
        *(uint2*)(sT + n * 72 + c4 * 4) = u;
    }
    __syncthreads();

    int lane = tid & 31, w = tid >> 5;
    u32 sTu  = smem_u32(sT);
    u32 sW1u = smem_u32(sW1);
    u32 sW2u = smem_u32(sW2);
    u32 aAddr  = sTu  + ((w * 16 + (lane & 15)) * 72 + (lane >> 4) * 8) * 2;
    u32 b1Addr = sW1u + ((lane & 15) * 72 + (lane >> 4) * 8) * 2;
    u32 b2Addr = sW2u + ((lane & 15) * 72 + (lane >> 4) * 8) * 2;

    int r0loc = w * 16 + (lane >> 2);
    int r1loc = r0loc + 8;

    float acc[8][4];
#pragma unroll
    for (int j = 0; j < 8; j++) {
        acc[j][0] = 0.f; acc[j][1] = 0.f; acc[j][2] = 0.f; acc[j][3] = 0.f;
    }

    // ---- layer 1 ----
#pragma unroll
    for (int ks = 0; ks < 4; ks++) {
        u32 a0, a1, a2, a3;
        ldsm_x4(a0, a1, a2, a3, aAddr + ks * 32);
#pragma unroll
        for (int jp = 0; jp < 4; jp++) {
            u32 b0, b1r, b2, b3;
            ldsm_x4_t(b0, b1r, b2, b3, b1Addr + ks * (16 * 72 * 2) + jp * 32);
            mma16816(acc[2 * jp],     a0, a1, a2, a3, b0, b1r);
            mma16816(acc[2 * jp + 1], a0, a1, a2, a3, b2, b3);
        }
    }
    __syncthreads();   // everyone done reading sT before overwrite

    // bias + relu, repack h into sT as fp16
#pragma unroll
    for (int j = 0; j < 8; j++) {
        int ch = j * 8 + (lane & 3) * 2;
        float2 bb = *(const float2*)(b1 + ch);
        float h00 = fmaxf(acc[j][0] + bb.x, 0.f);
        float h01 = fmaxf(acc[j][1] + bb.y, 0.f);
        float h10 = fmaxf(acc[j][2] + bb.x, 0.f);
        float h11 = fmaxf(acc[j][3] + bb.y, 0.f);
        *(__half2*)(sT + r0loc * 72 + ch) = __floats2half2_rn(h00, h01);
        *(__half2*)(sT + r1loc * 72 + ch) = __floats2half2_rn(h10, h11);
    }
    __syncthreads();

    // ---- layer 2 ----
#pragma unroll
    for (int j = 0; j < 8; j++) {
        acc[j][0] = 0.f; acc[j][1] = 0.f; acc[j][2] = 0.f; acc[j][3] = 0.f;
    }
#pragma unroll
    for (int ks = 0; ks < 4; ks++) {
        u32 a0, a1, a2, a3;
        ldsm_x4(a0, a1, a2, a3, aAddr + ks * 32);
#pragma unroll
        for (int jp = 0; jp < 4; jp++) {
            u32 b0, b1r, b2, b3;
            ldsm_x4_t(b0, b1r, b2, b3, b2Addr + ks * (16 * 72 * 2) + jp * 32);
            mma16816(acc[2 * jp],     a0, a1, a2, a3, b0, b1r);
            mma16816(acc[2 * jp + 1], a0, a1, a2, a3, b2, b3);
        }
    }

    int r0 = base + r0loc;
    int r1 = base + r1loc;
#pragma unroll
    for (int j = 0; j < 8; j++) {
        int ch = j * 8 + (lane & 3) * 2;
        float2 bb = *(const float2*)(b2 + ch);
        if (r0 < N)
            *(float2*)(out + (size_t)r0 * 64 + ch) =
                make_float2(acc[j][0] + bb.x, acc[j][1] + bb.y);
        if (r1 < N)
            *(float2*)(out + (size_t)r1 * 64 + ch) =
                make_float2(acc[j][2] + bb.x, acc[j][3] + bb.y);
    }
}

extern "C" void kernel_launch(void* const* d_in, const int* in_sizes, int n_in,
                              void* d_out, int out_size) {
    const float* x    = (const float*)d_in[0];
    const float* pos  = (const float*)d_in[1];
    const int*   ei   = (const int*)d_in[2];
    const float* Wl   = (const float*)d_in[3];
    const float* Wsrc = (const float*)d_in[4];
    // d_in[5] = W_dst  (unused: cancels exactly in the segment softmax)
    const float* Wpos = (const float*)d_in[6];
    const float* bpos = (const float*)d_in[7];
    const float* W1   = (const float*)d_in[8];
    const float* b1   = (const float*)d_in[9];
    const float* W2   = (const float*)d_in[10];
    const float* b2   = (const float*)d_in[11];
    float* out = (float*)d_out;

    int N  = in_sizes[0] / 64;
    int E  = in_sizes[2] / 2;

    int nodeBlocks = (N + 127) / 128;
    int histBlocks = (E + 1023) / 1024;
    proj_kernel<<<nodeBlocks + histBlocks, 256>>>(x, pos, ei, Wl, Wsrc, bpos,
                                                  N, E, nodeBlocks);

    alloc_kernel<<<(N + 1023) / 1024, 1024>>>(N);

    scatter_kernel<<<(E + 255) / 256, 256>>>(ei, E);

    aggregate_kernel<<<(N * 32 + 255) / 256, 256>>>(Wpos, bpos, N);

    mlp_kernel<<<(N + 127) / 128, 256>>>(W1, b1, W2, b2, out, N);
}